// round 4
// baseline (speedup 1.0000x reference)
#include <cuda_runtime.h>

// Problem constants
#define BB 2
#define CC 64
#define HH 64
#define WW 128
#define HWN (HH*WW)         // 8192
#define NXG 512
#define NYG 512
#define NCELL (NXG*NYG)     // 262144
#define SCH 4               // near-point chunks for the kNN kernel
#define NCHUNK (HWN/SCH)    // 2048
#define POS_INF (3.402823466e38f)

// Scratch (device globals — no runtime allocation allowed)
__device__ float4 g_near[BB*HWN];            // packed near pts {x,y,z, valid ? |n|^2 : 1e30}
__device__ int    g_far_idx[BB*HWN];         // compacted valid far point indices
__device__ int    g_far_cnt[BB];
__device__ float  g_part_s[BB*SCH*3*HWN];    // partial top-3 d2 (ascending) [b][chunk][k][slot]
__device__ int    g_part_i[BB*SCH*3*HWN];    // partial top-3 indices
__device__ float  g_cnt[BB*NCELL];           // per-cell point counts

// Sorted-insert of smallest-3, strict '<' so earlier indices win ties
// (matches jax.lax.top_k stable tie-breaking on -d2)
#define INS(val, jj) do {                                             \
    if ((val) < s2) {                                                 \
        if ((val) < s1) {                                             \
            s2 = s1; i2 = i1;                                         \
            if ((val) < s0) { s1 = s0; i1 = i0; s0 = (val); i0 = (jj); } \
            else            { s1 = (val); i1 = (jj); }                \
        } else { s2 = (val); i2 = (jj); }                             \
    }                                                                 \
} while (0)

__device__ __forceinline__ int cell_x(float x) { return (int)floorf(__fdiv_rn(x, 0.1f)); }
__device__ __forceinline__ int cell_y(float y) { return (int)floorf(__fdiv_rn(__fsub_rn(y, -25.6f), 0.1f)); }

// |p|^2 with the reference's rounding: ((x*x + y*y) + z*z), no fma contraction
__device__ __forceinline__ float sqnorm_ref(float x, float y, float z) {
    return __fadd_rn(__fadd_rn(__fmul_rn(x, x), __fmul_rn(y, y)), __fmul_rn(z, z));
}

// GEMM-replica pair distance.
// Reference: d2 = (|f|^2 + |n|^2) - (2*f) @ n^T, where the GEMM (cublas/Eigen)
// accumulates k ascending with FMA: acc = rn(a0*b0); acc = fma(a1,b1,acc);
// acc = fma(a2,b2,acc). Pre-doubled f is bit-equal to the alpha=2 folded path
// (rounding commutes with exact powers of two).
__device__ __forceinline__ float d2_ref(float fx2, float fy2, float fz2, float fsq,
                                        float nx, float ny, float nz, float nsq) {
    float acc = __fmul_rn(fx2, nx);
    acc = __fmaf_rn(fy2, ny, acc);
    acc = __fmaf_rn(fz2, nz, acc);
    return __fsub_rn(__fadd_rn(fsq, nsq), acc);
}

// ---------------------------------------------------------------------------
// 1. prep: pack near points (+validity), compact valid-in-range far points
// ---------------------------------------------------------------------------
__global__ void prep_kernel(const float* __restrict__ pif_near,
                            const int*   __restrict__ mask_near,
                            const float* __restrict__ pif_far,
                            const int*   __restrict__ mask_far) {
    int t = blockIdx.x * blockDim.x + threadIdx.x;
    if (t >= BB*HWN) return;
    int b = t / HWN, p = t % HWN;

    const float* pn = pif_near + (size_t)b * 4 * HWN;
    float x = pn[p], y = pn[HWN + p], z = pn[2*HWN + p];
    float nsq = sqnorm_ref(x, y, z);
    bool v = mask_near[t] > 0;
    // invalid -> w so large that d2 ~ 1e30, never in top-3 (ref masks to 1e10)
    g_near[t] = make_float4(x, y, z, v ? nsq : 1e30f);

    if (mask_far[t] > 0) {
        const float* pf = pif_far + (size_t)b * 4 * HWN;
        float fx = pf[p], fy = pf[HWN + p];
        int ix = cell_x(fx), iy = cell_y(fy);
        if (ix >= 0 && ix < NXG && iy >= 0 && iy < NYG) {
            int pos = atomicAdd(&g_far_cnt[b], 1);
            g_far_idx[b*HWN + pos] = p;
        }
    }
}

// ---------------------------------------------------------------------------
// 2. near-point scatter: sums into d_out, counts into g_cnt
// ---------------------------------------------------------------------------
__global__ void near_scatter_kernel(const float* __restrict__ fv,
                                    const float* __restrict__ pif_near,
                                    const int*   __restrict__ mask_near,
                                    float* __restrict__ out) {
    int t = blockIdx.x * blockDim.x + threadIdx.x;
    if (t >= BB*HWN) return;
    int b = t / HWN, p = t % HWN;
    if (mask_near[t] <= 0) return;

    const float* pn = pif_near + (size_t)b * 4 * HWN;
    float x = pn[p], y = pn[HWN + p];
    int ix = cell_x(x), iy = cell_y(y);
    if (ix < 0 || ix >= NXG || iy < 0 || iy >= NYG) return;
    int cell = iy * NXG + ix;

    atomicAdd(&g_cnt[b*NCELL + cell], 1.0f);
    const float* f0 = fv + (size_t)b * CC * HWN + p;
    float* ob = out + (size_t)b * CC * NCELL + cell;
    #pragma unroll 8
    for (int c = 0; c < CC; c++)
        atomicAdd(ob + (size_t)c * NCELL, f0[(size_t)c * HWN]);
}

// ---------------------------------------------------------------------------
// 3. kNN: each thread owns one compacted far point, scans a near-chunk from
//    smem, keeps running 3-smallest of d2 (GEMM-replica rounding).
// ---------------------------------------------------------------------------
__global__ void __launch_bounds__(256) knn_kernel(const float* __restrict__ pif_far) {
    __shared__ float4 sh[NCHUNK];
    int b  = blockIdx.z;
    int ch = blockIdx.y;
    int nbase = ch * NCHUNK;

    const float4* src = g_near + b*HWN + nbase;
    for (int i = threadIdx.x; i < NCHUNK; i += 256)
        sh[i] = src[i];
    __syncthreads();

    int slot = blockIdx.x * 256 + threadIdx.x;
    if (slot >= g_far_cnt[b]) return;
    int p = g_far_idx[b*HWN + slot];

    const float* pf = pif_far + (size_t)b * 4 * HWN;
    float x = pf[p], y = pf[HWN + p], z = pf[2*HWN + p];
    float fsq = sqnorm_ref(x, y, z);
    float fx2 = 2.0f * x, fy2 = 2.0f * y, fz2 = 2.0f * z;  // exact

    float s0 = POS_INF, s1 = POS_INF, s2 = POS_INF;
    int   i0 = 0, i1 = 0, i2 = 0;

    #pragma unroll 1
    for (int j = 0; j < NCHUNK; j += 4) {
        float4 q0 = sh[j];
        float4 q1 = sh[j+1];
        float4 q2 = sh[j+2];
        float4 q3 = sh[j+3];
        float d0  = d2_ref(fx2, fy2, fz2, fsq, q0.x, q0.y, q0.z, q0.w);
        float d1  = d2_ref(fx2, fy2, fz2, fsq, q1.x, q1.y, q1.z, q1.w);
        float d2v = d2_ref(fx2, fy2, fz2, fsq, q2.x, q2.y, q2.z, q2.w);
        float d3  = d2_ref(fx2, fy2, fz2, fsq, q3.x, q3.y, q3.z, q3.w);
        float m = fminf(fminf(d0, d1), fminf(d2v, d3));
        if (m < s2) {   // rarely taken (~3*ln(N) per chunk)
            INS(d0, nbase + j);
            INS(d1, nbase + j + 1);
            INS(d2v, nbase + j + 2);
            INS(d3, nbase + j + 3);
        }
    }

    int base = ((b*SCH + ch) * 3) * HWN + slot;
    g_part_s[base        ] = s0;  g_part_i[base        ] = i0;
    g_part_s[base +   HWN] = s1;  g_part_i[base +   HWN] = i1;
    g_part_s[base + 2*HWN] = s2;  g_part_i[base + 2*HWN] = i2;
}

// ---------------------------------------------------------------------------
// 4. merge partial top-3s, compute IDW weights (reference rounding),
//    gather+interpolate 64 ch, scatter into BEV (+count)
// ---------------------------------------------------------------------------
__global__ void epi_kernel(const float* __restrict__ fv,
                           const float* __restrict__ pif_far,
                           float* __restrict__ out) {
    int t = blockIdx.x * blockDim.x + threadIdx.x;
    if (t >= BB*HWN) return;
    int b = t / HWN, slot = t % HWN;
    if (slot >= g_far_cnt[b]) return;
    int p = g_far_idx[b*HWN + slot];

    float s0 = POS_INF, s1 = POS_INF, s2 = POS_INF;
    int   i0 = 0, i1 = 0, i2 = 0;
    #pragma unroll
    for (int ch = 0; ch < SCH; ch++) {
        int base = ((b*SCH + ch) * 3) * HWN + slot;
        #pragma unroll
        for (int k = 0; k < 3; k++) {
            float v = g_part_s[base + k*HWN];
            int   jj = g_part_i[base + k*HWN];
            INS(v, jj);
        }
    }

    // IDW weights exactly as reference: r = 1/(d+1e-8); w = r / ((r0+r1)+r2)
    float r0 = __fdiv_rn(1.0f, __fadd_rn(s0, 1e-8f));
    float r1 = __fdiv_rn(1.0f, __fadd_rn(s1, 1e-8f));
    float r2 = __fdiv_rn(1.0f, __fadd_rn(s2, 1e-8f));
    float rs = __fadd_rn(__fadd_rn(r0, r1), r2);
    float w0 = __fdiv_rn(r0, rs), w1 = __fdiv_rn(r1, rs), w2 = __fdiv_rn(r2, rs);

    const float* pf = pif_far + (size_t)b * 4 * HWN;
    float x = pf[p], y = pf[HWN + p];
    int ix = cell_x(x), iy = cell_y(y);     // guaranteed in range by compaction
    int cell = iy * NXG + ix;

    atomicAdd(&g_cnt[b*NCELL + cell], 1.0f);
    const float* f0 = fv + (size_t)b * CC * HWN;
    float* ob = out + (size_t)b * CC * NCELL + cell;
    #pragma unroll 4
    for (int c = 0; c < CC; c++) {
        const float* fc = f0 + (size_t)c * HWN;
        // einsum order: (w0*g0 + w1*g1) + w2*g2, no fma
        float f = __fadd_rn(__fadd_rn(__fmul_rn(w0, fc[i0]), __fmul_rn(w1, fc[i1])),
                            __fmul_rn(w2, fc[i2]));
        atomicAdd(ob + (size_t)c * NCELL, f);
    }
}

// ---------------------------------------------------------------------------
// 5. divide: only cells with cnt >= 2 need a fixup
// ---------------------------------------------------------------------------
__global__ void div_kernel(float* __restrict__ out) {
    int t = blockIdx.x * blockDim.x + threadIdx.x;
    if (t >= BB*NCELL) return;
    float c = g_cnt[t];
    if (c >= 2.0f) {
        int b = t / NCELL, cell = t % NCELL;
        float* ob = out + (size_t)b * CC * NCELL + cell;
        #pragma unroll 8
        for (int ch = 0; ch < CC; ch++)
            ob[(size_t)ch * NCELL] = __fdiv_rn(ob[(size_t)ch * NCELL], c);
    }
}

extern "C" void kernel_launch(void* const* d_in, const int* in_sizes, int n_in,
                              void* d_out, int out_size) {
    const float* fv    = (const float*)d_in[0];   // (B,C,H,W)
    const float* pif   = (const float*)d_in[1];   // (B,4,H,W)
    const int*   mask  = (const int*)  d_in[2];   // (B,H,W)
    const float* piff  = (const float*)d_in[3];   // (B,4,H,W)
    const int*   maskf = (const int*)  d_in[4];   // (B,H,W)
    float* out = (float*)d_out;                   // (B,C,NY,NX)

    void *p_cnt = nullptr, *p_fcnt = nullptr;
    cudaGetSymbolAddress(&p_cnt, g_cnt);
    cudaGetSymbolAddress(&p_fcnt, g_far_cnt);

    cudaMemsetAsync(d_out, 0, (size_t)BB*CC*NCELL*sizeof(float));
    cudaMemsetAsync(p_cnt, 0, (size_t)BB*NCELL*sizeof(float));
    cudaMemsetAsync(p_fcnt, 0, BB*sizeof(int));

    prep_kernel<<<(BB*HWN + 255)/256, 256>>>(pif, mask, piff, maskf);
    near_scatter_kernel<<<(BB*HWN + 255)/256, 256>>>(fv, pif, mask, out);

    dim3 g(HWN/256, SCH, BB);   // 32 far-blocks x 4 near-chunks x 2 batches
    knn_kernel<<<g, 256>>>(piff);

    epi_kernel<<<(BB*HWN + 255)/256, 256>>>(fv, piff, out);
    div_kernel<<<(BB*NCELL + 255)/256, 256>>>(out);
}